// round 4
// baseline (speedup 1.0000x reference)
#include <cuda_runtime.h>
#include <cstdint>

// Problem constants (fixed shapes)
#define B 8
#define N 2048
#define F 128            // F_IN == F_OUT == 128
#define MAXN 192         // max neighbors per row (mean ~42)
#define ALPHA 0.2f

// Scratch (no cudaMalloc allowed)
__device__ float g_h[B * N * F];        // 8 MB
__device__ float g_esrc[B * N];
__device__ float g_edst[B * N];
__device__ int   g_nbr[N * MAXN];
__device__ int   g_nnz[N];

// ---------------------------------------------------------------------------
// tf32 helpers
// ---------------------------------------------------------------------------
__device__ __forceinline__ uint32_t f32_to_tf32(float x) {
    uint32_t r;
    asm("cvt.rna.tf32.f32 %0, %1;" : "=r"(r) : "f"(x));
    return r;
}
__device__ __forceinline__ void split_tf32(float x, uint32_t& hi, uint32_t& lo) {
    hi = f32_to_tf32(x);
    float rem = x - __uint_as_float(hi);
    lo = f32_to_tf32(rem);
}
__device__ __forceinline__ void mma_tf32(float& c0, float& c1, float& c2, float& c3,
                                         uint32_t a0, uint32_t a1, uint32_t a2, uint32_t a3,
                                         uint32_t b0, uint32_t b1) {
    asm volatile(
        "mma.sync.aligned.m16n8k8.row.col.f32.tf32.tf32.f32 "
        "{%0,%1,%2,%3}, {%4,%5,%6,%7}, {%8,%9}, {%0,%1,%2,%3};"
        : "+f"(c0), "+f"(c1), "+f"(c2), "+f"(c3)
        : "r"(a0), "r"(a1), "r"(a2), "r"(a3), "r"(b0), "r"(b1));
}

// ---------------------------------------------------------------------------
// Fat kernel: blocks [0,128)  -> tf32 split GEMM  h = x@W  (+ edge terms)
//             blocks [128,384) -> adjacency compaction
//
// GEMM: block tile 128 rows x 128 cols, 8 warps (16 rows each), K chunks of 32.
// Smem (dynamic, 67.5 KB): XThi/XTlo transposed [32 k][132], Whi/Wlo [32 k][132].
// Strides chosen so fragment LDS patterns (addr = 4*tig + gid + 8*nt mod 32)
// are bank-conflict-free.
// ---------------------------------------------------------------------------
#define GEMM_BLOCKS 128
#define ADJ_BLOCKS 256
#define MBLK 128
#define KCH 32
#define SSTRIDE 132
#define SBUF (KCH * SSTRIDE)    // 4224 floats per buffer

extern "C" __global__ __launch_bounds__(256) void fused_gemm_adj_kernel(
    const float* __restrict__ x,
    const float* __restrict__ adj,
    const float* __restrict__ W,
    const float* __restrict__ a_src,
    const float* __restrict__ a_dst) {

    if (blockIdx.x >= GEMM_BLOCKS) {
        // ---------------- adjacency compaction path ----------------
        int i = (blockIdx.x - GEMM_BLOCKS) * 8 + (threadIdx.x >> 5);
        int lane = threadIdx.x & 31;
        const float* row = adj + (size_t)i * N;
        int count = 0;
        for (int c = 0; c < N; c += 32) {
            int j = c + lane;
            bool p = (row[j] != 0.f) || (j == i);
            unsigned m = __ballot_sync(0xFFFFFFFFu, p);
            if (p) {
                int pos = count + __popc(m & ((1u << lane) - 1u));
                if (pos < MAXN) g_nbr[i * MAXN + pos] = j;
            }
            count += __popc(m);
        }
        if (lane == 0) g_nnz[i] = count < MAXN ? count : MAXN;
        return;
    }

    // ---------------- tf32 GEMM path ----------------
    extern __shared__ float smem[];
    float* XThi = smem;                 // [32][132] transposed: [k][row]
    float* XTlo = smem + SBUF;
    float* Whi  = smem + 2 * SBUF;      // [32][132]: [k][n]
    float* Wlo  = smem + 3 * SBUF;

    const int tid = threadIdx.x;
    const int w = tid >> 5;            // warp 0..7 -> rows w*16..w*16+15
    const int lane = tid & 31;
    const int gid = lane >> 2;         // group id 0..7
    const int tig = lane & 3;          // thread in group 0..3
    const int m0 = blockIdx.x * MBLK;

    float c[16][4];
#pragma unroll
    for (int nt = 0; nt < 16; nt++)
#pragma unroll
        for (int q = 0; q < 4; q++) c[nt][q] = 0.f;

    for (int k0 = 0; k0 < F; k0 += KCH) {
        // Load X chunk [128 rows x 32 k], transpose into XThi/XTlo.
        // 1024 float4 total, 4 per thread.
#pragma unroll
        for (int it = 0; it < 4; it++) {
            int idx = tid + it * 256;
            int row = idx >> 3;        // 0..127
            int c4 = idx & 7;          // float4 index along k (k = 4*c4..)
            float4 v = reinterpret_cast<const float4*>(
                x + (size_t)(m0 + row) * F + k0)[c4];
            float vv[4] = {v.x, v.y, v.z, v.w};
#pragma unroll
            for (int j = 0; j < 4; j++) {
                uint32_t hi, lo;
                split_tf32(vv[j], hi, lo);
                int k = c4 * 4 + j;
                XThi[k * SSTRIDE + row] = __uint_as_float(hi);
                XTlo[k * SSTRIDE + row] = __uint_as_float(lo);
            }
        }
        // Load W chunk [32 k x 128 n]. 1024 float4, 4 per thread.
#pragma unroll
        for (int it = 0; it < 4; it++) {
            int idx = tid + it * 256;
            int k = idx >> 5;          // 0..31
            int c4 = idx & 31;         // float4 along n
            float4 v = reinterpret_cast<const float4*>(
                W + (size_t)(k0 + k) * F)[c4];
            float vv[4] = {v.x, v.y, v.z, v.w};
            float hi4[4], lo4[4];
#pragma unroll
            for (int j = 0; j < 4; j++) {
                uint32_t hi, lo;
                split_tf32(vv[j], hi, lo);
                hi4[j] = __uint_as_float(hi);
                lo4[j] = __uint_as_float(lo);
            }
            reinterpret_cast<float4*>(Whi + k * SSTRIDE + c4 * 4)[0] =
                make_float4(hi4[0], hi4[1], hi4[2], hi4[3]);
            reinterpret_cast<float4*>(Wlo + k * SSTRIDE + c4 * 4)[0] =
                make_float4(lo4[0], lo4[1], lo4[2], lo4[3]);
        }
        __syncthreads();

#pragma unroll
        for (int kk = 0; kk < 4; kk++) {
            const int kb = kk * 8;
            const int wrow = w * 16;
            // A fragments (row-major 16x8): a0 (gid,tig) a1 (gid+8,tig)
            //                               a2 (gid,tig+4) a3 (gid+8,tig+4)
            uint32_t ah0 = __float_as_uint(XThi[(kb + tig) * SSTRIDE + wrow + gid]);
            uint32_t ah1 = __float_as_uint(XThi[(kb + tig) * SSTRIDE + wrow + gid + 8]);
            uint32_t ah2 = __float_as_uint(XThi[(kb + tig + 4) * SSTRIDE + wrow + gid]);
            uint32_t ah3 = __float_as_uint(XThi[(kb + tig + 4) * SSTRIDE + wrow + gid + 8]);
            uint32_t al0 = __float_as_uint(XTlo[(kb + tig) * SSTRIDE + wrow + gid]);
            uint32_t al1 = __float_as_uint(XTlo[(kb + tig) * SSTRIDE + wrow + gid + 8]);
            uint32_t al2 = __float_as_uint(XTlo[(kb + tig + 4) * SSTRIDE + wrow + gid]);
            uint32_t al3 = __float_as_uint(XTlo[(kb + tig + 4) * SSTRIDE + wrow + gid + 8]);
#pragma unroll
            for (int nt = 0; nt < 16; nt++) {
                // B fragments (col-major 8x8): b0 (k=tig, n=gid) b1 (k=tig+4, n=gid)
                int nb = nt * 8 + gid;
                uint32_t bh0 = __float_as_uint(Whi[(kb + tig) * SSTRIDE + nb]);
                uint32_t bh1 = __float_as_uint(Whi[(kb + tig + 4) * SSTRIDE + nb]);
                uint32_t bl0 = __float_as_uint(Wlo[(kb + tig) * SSTRIDE + nb]);
                uint32_t bl1 = __float_as_uint(Wlo[(kb + tig + 4) * SSTRIDE + nb]);
                mma_tf32(c[nt][0], c[nt][1], c[nt][2], c[nt][3],
                         ah0, ah1, ah2, ah3, bh0, bh1);
                mma_tf32(c[nt][0], c[nt][1], c[nt][2], c[nt][3],
                         ah0, ah1, ah2, ah3, bl0, bl1);
                mma_tf32(c[nt][0], c[nt][1], c[nt][2], c[nt][3],
                         al0, al1, al2, al3, bh0, bh1);
            }
        }
        __syncthreads();
    }

    // Epilogue: store h + fused edge terms.
    // Thread holds rows r0 = m0 + w*16 + gid and r0+8, cols nt*8 + 2*tig (+1).
    const int r0 = m0 + w * 16 + gid;
    float ss0 = 0.f, sd0 = 0.f, ss1 = 0.f, sd1 = 0.f;
#pragma unroll
    for (int nt = 0; nt < 16; nt++) {
        int col = nt * 8 + tig * 2;
        // store
        reinterpret_cast<float2*>(g_h + (size_t)r0 * F + col)[0] =
            make_float2(c[nt][0], c[nt][1]);
        reinterpret_cast<float2*>(g_h + (size_t)(r0 + 8) * F + col)[0] =
            make_float2(c[nt][2], c[nt][3]);
        // edge partials
        float as0 = a_src[col], as1 = a_src[col + 1];
        float ad0 = a_dst[col], ad1 = a_dst[col + 1];
        ss0 += c[nt][0] * as0 + c[nt][1] * as1;
        sd0 += c[nt][0] * ad0 + c[nt][1] * ad1;
        ss1 += c[nt][2] * as0 + c[nt][3] * as1;
        sd1 += c[nt][2] * ad0 + c[nt][3] * ad1;
    }
    // reduce across the 4 lanes sharing a row (tig dimension)
#pragma unroll
    for (int o = 1; o <= 2; o <<= 1) {
        ss0 += __shfl_xor_sync(0xFFFFFFFFu, ss0, o);
        sd0 += __shfl_xor_sync(0xFFFFFFFFu, sd0, o);
        ss1 += __shfl_xor_sync(0xFFFFFFFFu, ss1, o);
        sd1 += __shfl_xor_sync(0xFFFFFFFFu, sd1, o);
    }
    if (tig == 0) {
        g_esrc[r0] = ss0;
        g_edst[r0] = sd0;
        g_esrc[r0 + 8] = ss1;
        g_edst[r0 + 8] = sd1;
    }
}

// ---------------------------------------------------------------------------
// Kernel 2: warp-per-(b,i) sparse softmax + float4 gather-aggregate + ELU.
// ---------------------------------------------------------------------------
#define AGG_WARPS 8
__global__ __launch_bounds__(256) void agg_kernel(float* __restrict__ out) {
    __shared__ int   s_idx[AGG_WARPS][MAXN];
    __shared__ float s_w[AGG_WARPS][MAXN];

    const int w = threadIdx.x >> 5;
    const int lane = threadIdx.x & 31;
    const int wg = blockIdx.x * AGG_WARPS + w;   // global row id in [0, B*N)
    const int b = wg >> 11;                      // / 2048
    const int i = wg & (N - 1);

    const int nnz = g_nnz[i];
    const float ei = g_esrc[wg];
    const float* __restrict__ edst_b = g_edst + b * N;
    const int* __restrict__ nbr = g_nbr + i * MAXN;

    // Pass 1: logits -> shared, warp max
    float m = -1e30f;
    for (int j = lane; j < nnz; j += 32) {
        int col = nbr[j];
        float v = ei + edst_b[col];
        v = (v >= 0.f) ? v : ALPHA * v;   // LeakyReLU
        s_idx[w][j] = col;
        s_w[w][j] = v;
        m = fmaxf(m, v);
    }
#pragma unroll
    for (int o = 16; o; o >>= 1) m = fmaxf(m, __shfl_xor_sync(0xFFFFFFFFu, m, o));

    __syncwarp();
    // Pass 2: exp + warp sum
    float sum = 0.f;
    for (int j = lane; j < nnz; j += 32) {
        float e = expf(s_w[w][j] - m);
        s_w[w][j] = e;
        sum += e;
    }
#pragma unroll
    for (int o = 16; o; o >>= 1) sum += __shfl_xor_sync(0xFFFFFFFFu, sum, o);
    const float inv = 1.f / sum;
    __syncwarp();

    // Pass 3: gather-aggregate. Each lane: float4 over cols [lane*4, lane*4+4).
    const float* __restrict__ hb = g_h + (size_t)b * N * F;
    float4 acc = {0.f, 0.f, 0.f, 0.f};
    int j = 0;
    for (; j + 4 <= nnz; j += 4) {
        int i0 = s_idx[w][j + 0], i1 = s_idx[w][j + 1];
        int i2 = s_idx[w][j + 2], i3 = s_idx[w][j + 3];
        float w0 = s_w[w][j + 0], w1 = s_w[w][j + 1];
        float w2 = s_w[w][j + 2], w3 = s_w[w][j + 3];
        float4 v0 = reinterpret_cast<const float4*>(hb + (size_t)i0 * F)[lane];
        float4 v1 = reinterpret_cast<const float4*>(hb + (size_t)i1 * F)[lane];
        float4 v2 = reinterpret_cast<const float4*>(hb + (size_t)i2 * F)[lane];
        float4 v3 = reinterpret_cast<const float4*>(hb + (size_t)i3 * F)[lane];
        acc.x += w0 * v0.x; acc.y += w0 * v0.y; acc.z += w0 * v0.z; acc.w += w0 * v0.w;
        acc.x += w1 * v1.x; acc.y += w1 * v1.y; acc.z += w1 * v1.z; acc.w += w1 * v1.w;
        acc.x += w2 * v2.x; acc.y += w2 * v2.y; acc.z += w2 * v2.z; acc.w += w2 * v2.w;
        acc.x += w3 * v3.x; acc.y += w3 * v3.y; acc.z += w3 * v3.z; acc.w += w3 * v3.w;
    }
    for (; j < nnz; j++) {
        int ij = s_idx[w][j];
        float wj = s_w[w][j];
        float4 v = reinterpret_cast<const float4*>(hb + (size_t)ij * F)[lane];
        acc.x += wj * v.x; acc.y += wj * v.y; acc.z += wj * v.z; acc.w += wj * v.w;
    }

    acc.x *= inv; acc.y *= inv; acc.z *= inv; acc.w *= inv;
    // ELU (alpha = 1)
    float4 r;
    r.x = (acc.x > 0.f) ? acc.x : expm1f(acc.x);
    r.y = (acc.y > 0.f) ? acc.y : expm1f(acc.y);
    r.z = (acc.z > 0.f) ? acc.z : expm1f(acc.z);
    r.w = (acc.w > 0.f) ? acc.w : expm1f(acc.w);
    reinterpret_cast<float4*>(out + (size_t)wg * F)[lane] = r;
}

// ---------------------------------------------------------------------------
extern "C" void kernel_launch(void* const* d_in, const int* in_sizes, int n_in,
                              void* d_out, int out_size) {
    const float* x     = (const float*)d_in[0];  // [B, N, F]
    const float* adj   = (const float*)d_in[1];  // [N, N]
    const float* W     = (const float*)d_in[2];  // [F, F]
    const float* a_src = (const float*)d_in[3];  // [F]
    const float* a_dst = (const float*)d_in[4];  // [F]
    float* out = (float*)d_out;                  // [B, N, F]

    (void)in_sizes; (void)n_in; (void)out_size;

    const int smem_bytes = 4 * SBUF * sizeof(float);   // 67584
    cudaFuncSetAttribute(fused_gemm_adj_kernel,
                         cudaFuncAttributeMaxDynamicSharedMemorySize, smem_bytes);

    fused_gemm_adj_kernel<<<GEMM_BLOCKS + ADJ_BLOCKS, 256, smem_bytes>>>(
        x, adj, W, a_src, a_dst);
    agg_kernel<<<(B * N) / AGG_WARPS, 256>>>(out);
}

// round 5
// speedup vs baseline: 1.0356x; 1.0356x over previous
#include <cuda_runtime.h>
#include <cuda_fp16.h>
#include <cstdint>

// Problem constants (fixed shapes)
#define B 8
#define N 2048
#define F 128            // F_IN == F_OUT == 128
#define MAXN 192         // max neighbors per row (mean ~42)
#define ALPHA 0.2f

// Scratch (no cudaMalloc allowed)
__device__ __align__(16) __half g_hh[B * N * F];   // 4 MB, fp16 copy of h
__device__ float g_esrc[B * N];
__device__ float g_edst[B * N];
__device__ int   g_nbr[N * MAXN];
__device__ int   g_nnz[N];

// ---------------------------------------------------------------------------
// Kernel 1: h = x @ W (fp32 accum, fp16 store) fused with e_src/e_dst.
// Tile: 32 rows x 128 cols, TK=32, 4x8 micro-tile, 128 threads, grid 512.
// ---------------------------------------------------------------------------
#define TM 32
#define TK 32
#define XSTR 33
#define WSTR 132

__global__ __launch_bounds__(128) void gemm_edge_kernel(const float* __restrict__ x,
                                                        const float* __restrict__ W,
                                                        const float* __restrict__ a_src,
                                                        const float* __restrict__ a_dst) {
    __shared__ float Xs[TM * XSTR];   // [row][k]: row*33 + k
    __shared__ float Ws[TK * WSTR];   // [k][n]:   k*132 + n

    const int tid = threadIdx.x;
    const int tx = tid & 15;          // col group: 8 cols (tx*8 ..)
    const int ty = tid >> 4;          // row group: 4 rows (ty*4 ..)
    const int m0 = blockIdx.x * TM;

    float acc[4][8];
#pragma unroll
    for (int i = 0; i < 4; i++)
#pragma unroll
        for (int j = 0; j < 8; j++) acc[i][j] = 0.f;

#pragma unroll
    for (int k0 = 0; k0 < F; k0 += TK) {
        // X tile: 32 rows x 32 k = 256 float4, 2 per thread
#pragma unroll
        for (int l = tid; l < TM * TK / 4; l += 128) {
            int row = l >> 3;
            int c4 = l & 7;
            float4 v = reinterpret_cast<const float4*>(
                x + (size_t)(m0 + row) * F + k0)[c4];
            float* d = Xs + row * XSTR + c4 * 4;
            d[0] = v.x; d[1] = v.y; d[2] = v.z; d[3] = v.w;
        }
        // W tile: 32 k x 128 n = 1024 float4, 8 per thread (aligned: 132%4==0)
#pragma unroll
        for (int l = tid; l < TK * F / 4; l += 128) {
            int kk = l >> 5;
            int c4 = l & 31;
            reinterpret_cast<float4*>(Ws + kk * WSTR + c4 * 4)[0] =
                reinterpret_cast<const float4*>(W + (size_t)(k0 + kk) * F)[c4];
        }
        __syncthreads();

#pragma unroll 8
        for (int kk = 0; kk < TK; kk++) {
            float xv[4];
#pragma unroll
            for (int i = 0; i < 4; i++) xv[i] = Xs[(ty * 4 + i) * XSTR + kk];
            float4 w0 = *reinterpret_cast<float4*>(&Ws[kk * WSTR + tx * 8]);
            float4 w1 = *reinterpret_cast<float4*>(&Ws[kk * WSTR + tx * 8 + 4]);
            float wv[8] = {w0.x, w0.y, w0.z, w0.w, w1.x, w1.y, w1.z, w1.w};
#pragma unroll
            for (int i = 0; i < 4; i++)
#pragma unroll
                for (int j = 0; j < 8; j++) acc[i][j] += xv[i] * wv[j];
        }
        __syncthreads();
    }

    // Store h as fp16 (8 halfs = 16B per row-slice per thread)
#pragma unroll
    for (int i = 0; i < 4; i++) {
        int r = m0 + ty * 4 + i;
        __half2 p0 = __floats2half2_rn(acc[i][0], acc[i][1]);
        __half2 p1 = __floats2half2_rn(acc[i][2], acc[i][3]);
        __half2 p2 = __floats2half2_rn(acc[i][4], acc[i][5]);
        __half2 p3 = __floats2half2_rn(acc[i][6], acc[i][7]);
        uint4 pk;
        pk.x = *reinterpret_cast<uint32_t*>(&p0);
        pk.y = *reinterpret_cast<uint32_t*>(&p1);
        pk.z = *reinterpret_cast<uint32_t*>(&p2);
        pk.w = *reinterpret_cast<uint32_t*>(&p3);
        reinterpret_cast<uint4*>(g_hh + (size_t)r * F + tx * 8)[0] = pk;
    }

    // Fused edge terms: fp32, reduce over the 16 tx lanes (same ty = half warp).
    float asr[8], adt[8];
#pragma unroll
    for (int j = 0; j < 8; j++) {
        asr[j] = a_src[tx * 8 + j];
        adt[j] = a_dst[tx * 8 + j];
    }
#pragma unroll
    for (int i = 0; i < 4; i++) {
        float s = 0.f, d = 0.f;
#pragma unroll
        for (int j = 0; j < 8; j++) {
            s += acc[i][j] * asr[j];
            d += acc[i][j] * adt[j];
        }
#pragma unroll
        for (int o = 8; o; o >>= 1) {
            s += __shfl_down_sync(0xFFFFFFFFu, s, o, 16);
            d += __shfl_down_sync(0xFFFFFFFFu, d, o, 16);
        }
        if (tx == 0) {
            g_esrc[m0 + ty * 4 + i] = s;
            g_edst[m0 + ty * 4 + i] = d;
        }
    }
}

// ---------------------------------------------------------------------------
// Kernel 2: adjacency compaction (adj != 0 OR self-loop). One warp per row.
// ---------------------------------------------------------------------------
__global__ __launch_bounds__(256) void adj_kernel(const float* __restrict__ adj) {
    int i = (blockIdx.x * blockDim.x + threadIdx.x) >> 5;
    int lane = threadIdx.x & 31;
    if (i >= N) return;
    const float* row = adj + (size_t)i * N;
    int count = 0;
    for (int c = 0; c < N; c += 32) {
        int j = c + lane;
        bool p = (row[j] != 0.f) || (j == i);
        unsigned m = __ballot_sync(0xFFFFFFFFu, p);
        if (p) {
            int pos = count + __popc(m & ((1u << lane) - 1u));
            if (pos < MAXN) g_nbr[i * MAXN + pos] = j;
        }
        count += __popc(m);
    }
    if (lane == 0) g_nnz[i] = count < MAXN ? count : MAXN;
}

// ---------------------------------------------------------------------------
// Kernel 3: warp-per-(b,i) sparse softmax + fp16 gather-aggregate + ELU.
// Each lane owns 4 output cols; per neighbor: 1x LDG.64 (half2 x2).
// ---------------------------------------------------------------------------
#define AGG_WARPS 8
__global__ __launch_bounds__(256) void agg_kernel(float* __restrict__ out) {
    __shared__ int   s_idx[AGG_WARPS][MAXN];
    __shared__ float s_w[AGG_WARPS][MAXN];

    const int w = threadIdx.x >> 5;
    const int lane = threadIdx.x & 31;
    const int wg = blockIdx.x * AGG_WARPS + w;   // global row id in [0, B*N)
    const int b = wg >> 11;                      // / 2048
    const int i = wg & (N - 1);

    const int nnz = g_nnz[i];
    const float ei = g_esrc[wg];
    const float* __restrict__ edst_b = g_edst + b * N;
    const int* __restrict__ nbr = g_nbr + i * MAXN;

    // Pass 1: logits -> shared, warp max
    float m = -1e30f;
    for (int j = lane; j < nnz; j += 32) {
        int col = nbr[j];
        float v = ei + edst_b[col];
        v = (v >= 0.f) ? v : ALPHA * v;   // LeakyReLU
        s_idx[w][j] = col;
        s_w[w][j] = v;
        m = fmaxf(m, v);
    }
#pragma unroll
    for (int o = 16; o; o >>= 1) m = fmaxf(m, __shfl_xor_sync(0xFFFFFFFFu, m, o));

    __syncwarp();
    // Pass 2: exp + warp sum
    float sum = 0.f;
    for (int j = lane; j < nnz; j += 32) {
        float e = expf(s_w[w][j] - m);
        s_w[w][j] = e;
        sum += e;
    }
#pragma unroll
    for (int o = 16; o; o >>= 1) sum += __shfl_xor_sync(0xFFFFFFFFu, sum, o);
    const float inv = 1.f / sum;
    __syncwarp();

    // Pass 3: gather-aggregate (fp16 rows, fp32 accumulate).
    const __half* __restrict__ hb = g_hh + (size_t)b * N * F;
    float4 acc = {0.f, 0.f, 0.f, 0.f};
    int j = 0;
    for (; j + 4 <= nnz; j += 4) {
        int i0 = s_idx[w][j + 0], i1 = s_idx[w][j + 1];
        int i2 = s_idx[w][j + 2], i3 = s_idx[w][j + 3];
        float w0 = s_w[w][j + 0], w1 = s_w[w][j + 1];
        float w2 = s_w[w][j + 2], w3 = s_w[w][j + 3];
        uint2 r0 = reinterpret_cast<const uint2*>(hb + (size_t)i0 * F)[lane];
        uint2 r1 = reinterpret_cast<const uint2*>(hb + (size_t)i1 * F)[lane];
        uint2 r2 = reinterpret_cast<const uint2*>(hb + (size_t)i2 * F)[lane];
        uint2 r3 = reinterpret_cast<const uint2*>(hb + (size_t)i3 * F)[lane];
        float2 a0 = __half22float2(*reinterpret_cast<__half2*>(&r0.x));
        float2 b0 = __half22float2(*reinterpret_cast<__half2*>(&r0.y));
        float2 a1 = __half22float2(*reinterpret_cast<__half2*>(&r1.x));
        float2 b1 = __half22float2(*reinterpret_cast<__half2*>(&r1.y));
        float2 a2 = __half22float2(*reinterpret_cast<__half2*>(&r2.x));
        float2 b2 = __half22float2(*reinterpret_cast<__half2*>(&r2.y));
        float2 a3 = __half22float2(*reinterpret_cast<__half2*>(&r3.x));
        float2 b3 = __half22float2(*reinterpret_cast<__half2*>(&r3.y));
        acc.x += w0 * a0.x; acc.y += w0 * a0.y; acc.z += w0 * b0.x; acc.w += w0 * b0.y;
        acc.x += w1 * a1.x; acc.y += w1 * a1.y; acc.z += w1 * b1.x; acc.w += w1 * b1.y;
        acc.x += w2 * a2.x; acc.y += w2 * a2.y; acc.z += w2 * b2.x; acc.w += w2 * b2.y;
        acc.x += w3 * a3.x; acc.y += w3 * a3.y; acc.z += w3 * b3.x; acc.w += w3 * b3.y;
    }
    for (; j < nnz; j++) {
        int ij = s_idx[w][j];
        float wj = s_w[w][j];
        uint2 r = reinterpret_cast<const uint2*>(hb + (size_t)ij * F)[lane];
        float2 a = __half22float2(*reinterpret_cast<__half2*>(&r.x));
        float2 bb = __half22float2(*reinterpret_cast<__half2*>(&r.y));
        acc.x += wj * a.x; acc.y += wj * a.y; acc.z += wj * bb.x; acc.w += wj * bb.y;
    }

    acc.x *= inv; acc.y *= inv; acc.z *= inv; acc.w *= inv;
    // ELU (alpha = 1)
    float4 r;
    r.x = (acc.x > 0.f) ? acc.x : expm1f(acc.x);
    r.y = (acc.y > 0.f) ? acc.y : expm1f(acc.y);
    r.z = (acc.z > 0.f) ? acc.z : expm1f(acc.z);
    r.w = (acc.w > 0.f) ? acc.w : expm1f(acc.w);
    reinterpret_cast<float4*>(out + (size_t)wg * F)[lane] = r;
}

// ---------------------------------------------------------------------------
extern "C" void kernel_launch(void* const* d_in, const int* in_sizes, int n_in,
                              void* d_out, int out_size) {
    const float* x     = (const float*)d_in[0];  // [B, N, F]
    const float* adj   = (const float*)d_in[1];  // [N, N]
    const float* W     = (const float*)d_in[2];  // [F, F]
    const float* a_src = (const float*)d_in[3];  // [F]
    const float* a_dst = (const float*)d_in[4];  // [F]
    float* out = (float*)d_out;                  // [B, N, F]

    (void)in_sizes; (void)n_in; (void)out_size;

    gemm_edge_kernel<<<(B * N) / TM, 128>>>(x, W, a_src, a_dst);
    adj_kernel<<<(N * 32) / 256, 256>>>(adj);
    agg_kernel<<<(B * N) / AGG_WARPS, 256>>>(out);
}

// round 6
// speedup vs baseline: 1.1777x; 1.1373x over previous
#include <cuda_runtime.h>
#include <cuda_fp16.h>
#include <cstdint>

// Problem constants (fixed shapes)
#define B 8
#define N 2048
#define F 128            // F_IN == F_OUT == 128
#define MAXN 192         // max neighbors per row (mean ~42)
#define ALPHA 0.2f

// Scratch (no cudaMalloc allowed)
__device__ __align__(16) __half g_hh[B * N * F];   // 4 MB, fp16 copy of h
__device__ float g_esrc[B * N];
__device__ float g_edst[B * N];
__device__ int   g_nbr[N * MAXN];
__device__ int   g_nnz[N];

// ---------------------------------------------------------------------------
// Fat kernel: blocks [0, 512)        -> GEMM h = x@W (+edge terms), 32 rows each
//             blocks [512, 512+1024) -> adjacency compaction, 2 rows each
// 64 threads per block.
// GEMM: tile 32 rows x 128 cols, TK=32, 8x8 register micro-tile.
// ---------------------------------------------------------------------------
#define GEMM_BLOCKS 512
#define ADJ_BLOCKS 1024
#define TM 32
#define TK 32
#define XSTR 33
#define WSTR 132

__global__ __launch_bounds__(64) void fused_gemm_adj_kernel(
    const float* __restrict__ x,
    const float* __restrict__ adj,
    const float* __restrict__ W,
    const float* __restrict__ a_src,
    const float* __restrict__ a_dst) {

    if (blockIdx.x >= GEMM_BLOCKS) {
        // ---------------- adjacency compaction path ----------------
        int i = (blockIdx.x - GEMM_BLOCKS) * 2 + (threadIdx.x >> 5);
        int lane = threadIdx.x & 31;
        const float* row = adj + (size_t)i * N;
        int count = 0;
        for (int c = 0; c < N; c += 32) {
            int j = c + lane;
            bool p = (row[j] != 0.f) || (j == i);
            unsigned m = __ballot_sync(0xFFFFFFFFu, p);
            if (p) {
                int pos = count + __popc(m & ((1u << lane) - 1u));
                if (pos < MAXN) g_nbr[i * MAXN + pos] = j;
            }
            count += __popc(m);
        }
        if (lane == 0) g_nnz[i] = count < MAXN ? count : MAXN;
        return;
    }

    // ---------------- GEMM path ----------------
    __shared__ float Xs[TM * XSTR];   // [row][k]: row*33 + k
    __shared__ float Ws[TK * WSTR];   // [k][n]:   k*132 + n

    const int tid = threadIdx.x;
    const int tx = tid & 15;          // col group: 8 cols (tx*8 ..)
    const int ty = tid >> 4;          // row group: 8 rows (ty*8 ..), 0..3
    const int m0 = blockIdx.x * TM;

    float acc[8][8];
#pragma unroll
    for (int i = 0; i < 8; i++)
#pragma unroll
        for (int j = 0; j < 8; j++) acc[i][j] = 0.f;

#pragma unroll
    for (int k0 = 0; k0 < F; k0 += TK) {
        // X tile: 32 rows x 32 k = 256 float4, 4 per thread
#pragma unroll
        for (int it = 0; it < 4; it++) {
            int l = tid + it * 64;
            int row = l >> 3;
            int c4 = l & 7;
            float4 v = reinterpret_cast<const float4*>(
                x + (size_t)(m0 + row) * F + k0)[c4];
            float* d = Xs + row * XSTR + c4 * 4;
            d[0] = v.x; d[1] = v.y; d[2] = v.z; d[3] = v.w;
        }
        // W tile: 32 k x 128 n = 1024 float4, 16 per thread
#pragma unroll
        for (int it = 0; it < 16; it++) {
            int l = tid + it * 64;
            int kk = l >> 5;
            int c4 = l & 31;
            reinterpret_cast<float4*>(Ws + kk * WSTR + c4 * 4)[0] =
                reinterpret_cast<const float4*>(W + (size_t)(k0 + kk) * F)[c4];
        }
        __syncthreads();

#pragma unroll 8
        for (int kk = 0; kk < TK; kk++) {
            float xv[8];
#pragma unroll
            for (int i = 0; i < 8; i++) xv[i] = Xs[(ty * 8 + i) * XSTR + kk];
            float4 w0 = *reinterpret_cast<float4*>(&Ws[kk * WSTR + tx * 8]);
            float4 w1 = *reinterpret_cast<float4*>(&Ws[kk * WSTR + tx * 8 + 4]);
            float wv[8] = {w0.x, w0.y, w0.z, w0.w, w1.x, w1.y, w1.z, w1.w};
#pragma unroll
            for (int i = 0; i < 8; i++)
#pragma unroll
                for (int j = 0; j < 8; j++) acc[i][j] += xv[i] * wv[j];
        }
        __syncthreads();
    }

    // Store h as fp16 (8 halfs = 16B per row-slice per thread)
#pragma unroll
    for (int i = 0; i < 8; i++) {
        int r = m0 + ty * 8 + i;
        __half2 p0 = __floats2half2_rn(acc[i][0], acc[i][1]);
        __half2 p1 = __floats2half2_rn(acc[i][2], acc[i][3]);
        __half2 p2 = __floats2half2_rn(acc[i][4], acc[i][5]);
        __half2 p3 = __floats2half2_rn(acc[i][6], acc[i][7]);
        uint4 pk;
        pk.x = *reinterpret_cast<uint32_t*>(&p0);
        pk.y = *reinterpret_cast<uint32_t*>(&p1);
        pk.z = *reinterpret_cast<uint32_t*>(&p2);
        pk.w = *reinterpret_cast<uint32_t*>(&p3);
        reinterpret_cast<uint4*>(g_hh + (size_t)r * F + tx * 8)[0] = pk;
    }

    // Fused edge terms: fp32, reduce over the 16 tx lanes (same ty = half warp).
    float asr[8], adt[8];
#pragma unroll
    for (int j = 0; j < 8; j++) {
        asr[j] = a_src[tx * 8 + j];
        adt[j] = a_dst[tx * 8 + j];
    }
#pragma unroll
    for (int i = 0; i < 8; i++) {
        float s = 0.f, d = 0.f;
#pragma unroll
        for (int j = 0; j < 8; j++) {
            s += acc[i][j] * asr[j];
            d += acc[i][j] * adt[j];
        }
#pragma unroll
        for (int o = 8; o; o >>= 1) {
            s += __shfl_down_sync(0xFFFFFFFFu, s, o, 16);
            d += __shfl_down_sync(0xFFFFFFFFu, d, o, 16);
        }
        if (tx == 0) {
            g_esrc[m0 + ty * 8 + i] = s;
            g_edst[m0 + ty * 8 + i] = d;
        }
    }
}

// ---------------------------------------------------------------------------
// Kernel 2: warp-per-(b,i) sparse softmax + fp16 gather-aggregate + ELU.
// Each lane owns 4 output cols; per neighbor: 1x LDG.64. Unroll 8 for MLP.
// ---------------------------------------------------------------------------
#define AGG_WARPS 8
__global__ __launch_bounds__(256) void agg_kernel(float* __restrict__ out) {
    __shared__ int   s_idx[AGG_WARPS][MAXN];
    __shared__ float s_w[AGG_WARPS][MAXN];

    const int w = threadIdx.x >> 5;
    const int lane = threadIdx.x & 31;
    const int wg = blockIdx.x * AGG_WARPS + w;   // global row id in [0, B*N)
    const int b = wg >> 11;                      // / 2048
    const int i = wg & (N - 1);

    const int nnz = g_nnz[i];
    const float ei = g_esrc[wg];
    const float* __restrict__ edst_b = g_edst + b * N;
    const int* __restrict__ nbr = g_nbr + i * MAXN;

    // Pass 1: logits -> shared, warp max
    float m = -1e30f;
    for (int j = lane; j < nnz; j += 32) {
        int col = nbr[j];
        float v = ei + edst_b[col];
        v = (v >= 0.f) ? v : ALPHA * v;   // LeakyReLU
        s_idx[w][j] = col;
        s_w[w][j] = v;
        m = fmaxf(m, v);
    }
#pragma unroll
    for (int o = 16; o; o >>= 1) m = fmaxf(m, __shfl_xor_sync(0xFFFFFFFFu, m, o));

    __syncwarp();
    // Pass 2: exp + warp sum
    float sum = 0.f;
    for (int j = lane; j < nnz; j += 32) {
        float e = expf(s_w[w][j] - m);
        s_w[w][j] = e;
        sum += e;
    }
#pragma unroll
    for (int o = 16; o; o >>= 1) sum += __shfl_xor_sync(0xFFFFFFFFu, sum, o);
    const float inv = 1.f / sum;
    __syncwarp();

    // Pass 3: gather-aggregate (fp16 rows, fp32 accumulate), unroll 8.
    const __half* __restrict__ hb = g_hh + (size_t)b * N * F;
    float4 acc = {0.f, 0.f, 0.f, 0.f};
    int j = 0;
    for (; j + 8 <= nnz; j += 8) {
        uint2 r[8];
        float wt[8];
#pragma unroll
        for (int q = 0; q < 8; q++) {
            int ij = s_idx[w][j + q];
            wt[q] = s_w[w][j + q];
            r[q] = reinterpret_cast<const uint2*>(hb + (size_t)ij * F)[lane];
        }
#pragma unroll
        for (int q = 0; q < 8; q++) {
            float2 a = __half22float2(*reinterpret_cast<__half2*>(&r[q].x));
            float2 bb = __half22float2(*reinterpret_cast<__half2*>(&r[q].y));
            acc.x += wt[q] * a.x;  acc.y += wt[q] * a.y;
            acc.z += wt[q] * bb.x; acc.w += wt[q] * bb.y;
        }
    }
    for (; j < nnz; j++) {
        int ij = s_idx[w][j];
        float wj = s_w[w][j];
        uint2 r = reinterpret_cast<const uint2*>(hb + (size_t)ij * F)[lane];
        float2 a = __half22float2(*reinterpret_cast<__half2*>(&r.x));
        float2 bb = __half22float2(*reinterpret_cast<__half2*>(&r.y));
        acc.x += wj * a.x; acc.y += wj * a.y; acc.z += wj * bb.x; acc.w += wj * bb.y;
    }

    acc.x *= inv; acc.y *= inv; acc.z *= inv; acc.w *= inv;
    // ELU (alpha = 1)
    float4 r;
    r.x = (acc.x > 0.f) ? acc.x : expm1f(acc.x);
    r.y = (acc.y > 0.f) ? acc.y : expm1f(acc.y);
    r.z = (acc.z > 0.f) ? acc.z : expm1f(acc.z);
    r.w = (acc.w > 0.f) ? acc.w : expm1f(acc.w);
    reinterpret_cast<float4*>(out + (size_t)wg * F)[lane] = r;
}

// ---------------------------------------------------------------------------
extern "C" void kernel_launch(void* const* d_in, const int* in_sizes, int n_in,
                              void* d_out, int out_size) {
    const float* x     = (const float*)d_in[0];  // [B, N, F]
    const float* adj   = (const float*)d_in[1];  // [N, N]
    const float* W     = (const float*)d_in[2];  // [F, F]
    const float* a_src = (const float*)d_in[3];  // [F]
    const float* a_dst = (const float*)d_in[4];  // [F]
    float* out = (float*)d_out;                  // [B, N, F]

    (void)in_sizes; (void)n_in; (void)out_size;

    fused_gemm_adj_kernel<<<GEMM_BLOCKS + ADJ_BLOCKS, 64>>>(x, adj, W, a_src, a_dst);
    agg_kernel<<<(B * N) / AGG_WARPS, 256>>>(out);
}

// round 7
// speedup vs baseline: 1.3039x; 1.1072x over previous
#include <cuda_runtime.h>
#include <cuda_fp16.h>
#include <cuda_bf16.h>
#include <cstdint>

// Problem constants (fixed shapes)
#define B 8
#define N 2048
#define F 128            // F_IN == F_OUT == 128
#define MAXN 192         // max neighbors per row (mean ~42)
#define ALPHA 0.2f

// Scratch (no cudaMalloc allowed)
__device__ __align__(16) __half g_hh[B * N * F];   // 4 MB, fp16 copy of h
__device__ float g_esrc[B * N];
__device__ float g_edst[B * N];
__device__ int   g_nbr[N * MAXN];
__device__ int   g_nnz[N];

// ---------------------------------------------------------------------------
// mma / ldmatrix helpers (sm_100a SIMT tensor path)
// ---------------------------------------------------------------------------
__device__ __forceinline__ void ldsm_x4(uint32_t* r, uint32_t addr) {
    asm volatile("ldmatrix.sync.aligned.m8n8.x4.shared.b16 {%0,%1,%2,%3}, [%4];"
                 : "=r"(r[0]), "=r"(r[1]), "=r"(r[2]), "=r"(r[3]) : "r"(addr));
}
__device__ __forceinline__ void ldsm_x4_t(uint32_t* r, uint32_t addr) {
    asm volatile("ldmatrix.sync.aligned.m8n8.x4.trans.shared.b16 {%0,%1,%2,%3}, [%4];"
                 : "=r"(r[0]), "=r"(r[1]), "=r"(r[2]), "=r"(r[3]) : "r"(addr));
}
__device__ __forceinline__ void mma_bf16(float* c, const uint32_t* a,
                                         uint32_t b0, uint32_t b1) {
    asm volatile(
        "mma.sync.aligned.m16n8k16.row.col.f32.bf16.bf16.f32 "
        "{%0,%1,%2,%3}, {%4,%5,%6,%7}, {%8,%9}, {%0,%1,%2,%3};"
        : "+f"(c[0]), "+f"(c[1]), "+f"(c[2]), "+f"(c[3])
        : "r"(a[0]), "r"(a[1]), "r"(a[2]), "r"(a[3]), "r"(b0), "r"(b1));
}
__device__ __forceinline__ uint32_t pack_bf16(__nv_bfloat16 a, __nv_bfloat16 b) {
    __nv_bfloat162 t;
    t.x = a; t.y = b;
    return *reinterpret_cast<uint32_t*>(&t);
}

// ---------------------------------------------------------------------------
// Fat kernel: blocks [0, 512)   -> bf16-split mma GEMM h = x@W (+edge terms)
//             blocks [512,1536) -> adjacency compaction, 2 rows each
// 64 threads (2 warps) per block. GEMM tile: M=32 (16/warp) x N=128, K chunks 32.
// ---------------------------------------------------------------------------
#define GEMM_BLOCKS 512
#define ADJ_BLOCKS 1024
#define TM 32
#define KCH 32
#define XSTR 40      // bf16 elems per X smem row  (banks: 20r mod 32 -> distinct)
#define WSTR 136     // bf16 elems per W smem row  (banks: 4r mod 32 -> distinct)

__global__ __launch_bounds__(64) void fused_gemm_adj_kernel(
    const float* __restrict__ x,
    const float* __restrict__ adj,
    const float* __restrict__ W,
    const float* __restrict__ a_src,
    const float* __restrict__ a_dst) {

    if (blockIdx.x >= GEMM_BLOCKS) {
        // ---------------- adjacency compaction path ----------------
        int i = (blockIdx.x - GEMM_BLOCKS) * 2 + (threadIdx.x >> 5);
        int lane = threadIdx.x & 31;
        const float* row = adj + (size_t)i * N;
        int count = 0;
        for (int c = 0; c < N; c += 32) {
            int j = c + lane;
            bool p = (row[j] != 0.f) || (j == i);
            unsigned m = __ballot_sync(0xFFFFFFFFu, p);
            if (p) {
                int pos = count + __popc(m & ((1u << lane) - 1u));
                if (pos < MAXN) g_nbr[i * MAXN + pos] = j;
            }
            count += __popc(m);
        }
        if (lane == 0) g_nnz[i] = count < MAXN ? count : MAXN;
        return;
    }

    // ---------------- GEMM path ----------------
    __shared__ __align__(16) __nv_bfloat16 Xhi[TM * XSTR];
    __shared__ __align__(16) __nv_bfloat16 Xlo[TM * XSTR];
    __shared__ __align__(16) __nv_bfloat16 Whi[KCH * WSTR];
    __shared__ __align__(16) __nv_bfloat16 Wlo[KCH * WSTR];

    const int tid = threadIdx.x;
    const int w = tid >> 5;
    const int lane = tid & 31;
    const int m0 = blockIdx.x * TM;

    // ldmatrix addressing (per-thread, constant across chunks)
    const int lm = lane >> 3;       // matrix id 0..3
    const int lr = lane & 7;        // row within matrix
    const int arow = w * 16 + ((lm & 1) << 3) + lr;
    const int acol = (lm >> 1) << 3;
    const int bk = ((lm & 1) << 3) + lr;
    const int bn = (lm >> 1) << 3;

    const uint32_t xhi_b = (uint32_t)__cvta_generic_to_shared(Xhi);
    const uint32_t xlo_b = (uint32_t)__cvta_generic_to_shared(Xlo);
    const uint32_t whi_b = (uint32_t)__cvta_generic_to_shared(Whi);
    const uint32_t wlo_b = (uint32_t)__cvta_generic_to_shared(Wlo);

    float c[16][4];
#pragma unroll
    for (int nt = 0; nt < 16; nt++)
#pragma unroll
        for (int q = 0; q < 4; q++) c[nt][q] = 0.f;

#pragma unroll
    for (int k0 = 0; k0 < F; k0 += KCH) {
        // ---- load + split X chunk [32 rows x 32 k] ----
#pragma unroll
        for (int it = 0; it < 4; it++) {
            int l = tid + it * 64;
            int row = l >> 3;       // 0..31
            int c4 = l & 7;
            float4 v = reinterpret_cast<const float4*>(
                x + (size_t)(m0 + row) * F + k0)[c4];
            float vv[4] = {v.x, v.y, v.z, v.w};
            __nv_bfloat16 hi[4], lo[4];
#pragma unroll
            for (int j = 0; j < 4; j++) {
                hi[j] = __float2bfloat16_rn(vv[j]);
                lo[j] = __float2bfloat16_rn(vv[j] - __bfloat162float(hi[j]));
            }
            int eoff = row * XSTR + c4 * 4;   // byte addr = row*80 + c4*8, 8-aligned
            uint2 ph = {pack_bf16(hi[0], hi[1]), pack_bf16(hi[2], hi[3])};
            uint2 pl = {pack_bf16(lo[0], lo[1]), pack_bf16(lo[2], lo[3])};
            *reinterpret_cast<uint2*>(Xhi + eoff) = ph;
            *reinterpret_cast<uint2*>(Xlo + eoff) = pl;
        }
        // ---- load + split W chunk [32 k x 128 n] ----
#pragma unroll
        for (int it = 0; it < 16; it++) {
            int l = tid + it * 64;
            int kk = l >> 5;        // 0..31
            int c4 = l & 31;
            float4 v = reinterpret_cast<const float4*>(
                W + (size_t)(k0 + kk) * F)[c4];
            float vv[4] = {v.x, v.y, v.z, v.w};
            __nv_bfloat16 hi[4], lo[4];
#pragma unroll
            for (int j = 0; j < 4; j++) {
                hi[j] = __float2bfloat16_rn(vv[j]);
                lo[j] = __float2bfloat16_rn(vv[j] - __bfloat162float(hi[j]));
            }
            int eoff = kk * WSTR + c4 * 4;    // byte addr = kk*272 + c4*8, 8-aligned
            uint2 ph = {pack_bf16(hi[0], hi[1]), pack_bf16(hi[2], hi[3])};
            uint2 pl = {pack_bf16(lo[0], lo[1]), pack_bf16(lo[2], lo[3])};
            *reinterpret_cast<uint2*>(Whi + eoff) = ph;
            *reinterpret_cast<uint2*>(Wlo + eoff) = pl;
        }
        __syncthreads();

        // ---- compute: 2 k-steps of 16 ----
#pragma unroll
        for (int ks = 0; ks < KCH; ks += 16) {
            uint32_t ah[4], al[4];
            uint32_t aoff = (uint32_t)((arow * XSTR + ks + acol) * 2);
            ldsm_x4(ah, xhi_b + aoff);
            ldsm_x4(al, xlo_b + aoff);
#pragma unroll
            for (int np = 0; np < 8; np++) {
                uint32_t bh[4], bl[4];
                uint32_t boff = (uint32_t)(((ks + bk) * WSTR + np * 16 + bn) * 2);
                ldsm_x4_t(bh, whi_b + boff);
                ldsm_x4_t(bl, wlo_b + boff);
                mma_bf16(c[2 * np],     ah, bh[0], bh[1]);
                mma_bf16(c[2 * np],     ah, bl[0], bl[1]);
                mma_bf16(c[2 * np],     al, bh[0], bh[1]);
                mma_bf16(c[2 * np + 1], ah, bh[2], bh[3]);
                mma_bf16(c[2 * np + 1], ah, bl[2], bl[3]);
                mma_bf16(c[2 * np + 1], al, bh[2], bh[3]);
            }
        }
        __syncthreads();
    }

    // ---- epilogue: h (fp16) store + fused edge terms ----
    const int gid = lane >> 2;     // row within 8
    const int tig = lane & 3;      // col pair selector
    const int r0 = m0 + w * 16 + gid;
    const int r1 = r0 + 8;

    float ss0 = 0.f, sd0 = 0.f, ss1 = 0.f, sd1 = 0.f;
#pragma unroll
    for (int nt = 0; nt < 16; nt++) {
        int col = nt * 8 + tig * 2;
        __half2 p0 = __floats2half2_rn(c[nt][0], c[nt][1]);
        __half2 p1 = __floats2half2_rn(c[nt][2], c[nt][3]);
        *reinterpret_cast<__half2*>(g_hh + (size_t)r0 * F + col) = p0;
        *reinterpret_cast<__half2*>(g_hh + (size_t)r1 * F + col) = p1;
        float as0 = a_src[col], as1 = a_src[col + 1];
        float ad0 = a_dst[col], ad1 = a_dst[col + 1];
        ss0 += c[nt][0] * as0 + c[nt][1] * as1;
        sd0 += c[nt][0] * ad0 + c[nt][1] * ad1;
        ss1 += c[nt][2] * as0 + c[nt][3] * as1;
        sd1 += c[nt][2] * ad0 + c[nt][3] * ad1;
    }
#pragma unroll
    for (int o = 1; o <= 2; o <<= 1) {
        ss0 += __shfl_xor_sync(0xFFFFFFFFu, ss0, o);
        sd0 += __shfl_xor_sync(0xFFFFFFFFu, sd0, o);
        ss1 += __shfl_xor_sync(0xFFFFFFFFu, ss1, o);
        sd1 += __shfl_xor_sync(0xFFFFFFFFu, sd1, o);
    }
    if (tig == 0) {
        g_esrc[r0] = ss0;
        g_edst[r0] = sd0;
        g_esrc[r1] = ss1;
        g_edst[r1] = sd1;
    }
}

// ---------------------------------------------------------------------------
// Kernel 2: warp-per-(b,i) sparse softmax + fp16 gather-aggregate + ELU.
// ---------------------------------------------------------------------------
#define AGG_WARPS 8
__global__ __launch_bounds__(256) void agg_kernel(float* __restrict__ out) {
    __shared__ int   s_idx[AGG_WARPS][MAXN];
    __shared__ float s_w[AGG_WARPS][MAXN];

    const int w = threadIdx.x >> 5;
    const int lane = threadIdx.x & 31;
    const int wg = blockIdx.x * AGG_WARPS + w;   // global row id in [0, B*N)
    const int b = wg >> 11;                      // / 2048
    const int i = wg & (N - 1);

    const int nnz = g_nnz[i];
    const float ei = g_esrc[wg];
    const float* __restrict__ edst_b = g_edst + b * N;
    const int* __restrict__ nbr = g_nbr + i * MAXN;

    // Pass 1: logits -> shared, warp max
    float m = -1e30f;
    for (int j = lane; j < nnz; j += 32) {
        int col = nbr[j];
        float v = ei + edst_b[col];
        v = (v >= 0.f) ? v : ALPHA * v;   // LeakyReLU
        s_idx[w][j] = col;
        s_w[w][j] = v;
        m = fmaxf(m, v);
    }
#pragma unroll
    for (int o = 16; o; o >>= 1) m = fmaxf(m, __shfl_xor_sync(0xFFFFFFFFu, m, o));

    __syncwarp();
    // Pass 2: exp + warp sum
    float sum = 0.f;
    for (int j = lane; j < nnz; j += 32) {
        float e = expf(s_w[w][j] - m);
        s_w[w][j] = e;
        sum += e;
    }
#pragma unroll
    for (int o = 16; o; o >>= 1) sum += __shfl_xor_sync(0xFFFFFFFFu, sum, o);
    const float inv = 1.f / sum;
    __syncwarp();

    // Pass 3: gather-aggregate (fp16 rows, fp32 accumulate), unroll 8.
    const __half* __restrict__ hb = g_hh + (size_t)b * N * F;
    float4 acc = {0.f, 0.f, 0.f, 0.f};
    int j = 0;
    for (; j + 8 <= nnz; j += 8) {
        uint2 r[8];
        float wt[8];
#pragma unroll
        for (int q = 0; q < 8; q++) {
            int ij = s_idx[w][j + q];
            wt[q] = s_w[w][j + q];
            r[q] = reinterpret_cast<const uint2*>(hb + (size_t)ij * F)[lane];
        }
#pragma unroll
        for (int q = 0; q < 8; q++) {
            float2 a = __half22float2(*reinterpret_cast<__half2*>(&r[q].x));
            float2 bb = __half22float2(*reinterpret_cast<__half2*>(&r[q].y));
            acc.x += wt[q] * a.x;  acc.y += wt[q] * a.y;
            acc.z += wt[q] * bb.x; acc.w += wt[q] * bb.y;
        }
    }
    for (; j < nnz; j++) {
        int ij = s_idx[w][j];
        float wj = s_w[w][j];
        uint2 r = reinterpret_cast<const uint2*>(hb + (size_t)ij * F)[lane];
        float2 a = __half22float2(*reinterpret_cast<__half2*>(&r.x));
        float2 bb = __half22float2(*reinterpret_cast<__half2*>(&r.y));
        acc.x += wj * a.x; acc.y += wj * a.y; acc.z += wj * bb.x; acc.w += wj * bb.y;
    }

    acc.x *= inv; acc.y *= inv; acc.z *= inv; acc.w *= inv;
    // ELU (alpha = 1)
    float4 r;
    r.x = (acc.x > 0.f) ? acc.x : expm1f(acc.x);
    r.y = (acc.y > 0.f) ? acc.y : expm1f(acc.y);
    r.z = (acc.z > 0.f) ? acc.z : expm1f(acc.z);
    r.w = (acc.w > 0.f) ? acc.w : expm1f(acc.w);
    reinterpret_cast<float4*>(out + (size_t)wg * F)[lane] = r;
}

// ---------------------------------------------------------------------------
extern "C" void kernel_launch(void* const* d_in, const int* in_sizes, int n_in,
                              void* d_out, int out_size) {
    const float* x     = (const float*)d_in[0];  // [B, N, F]
    const float* adj   = (const float*)d_in[1];  // [N, N]
    const float* W     = (const float*)d_in[2];  // [F, F]
    const float* a_src = (const float*)d_in[3];  // [F]
    const float* a_dst = (const float*)d_in[4];  // [F]
    float* out = (float*)d_out;                  // [B, N, F]

    (void)in_sizes; (void)n_in; (void)out_size;

    fused_gemm_adj_kernel<<<GEMM_BLOCKS + ADJ_BLOCKS, 64>>>(x, adj, W, a_src, a_dst);
    agg_kernel<<<(B * N) / AGG_WARPS, 256>>>(out);
}

// round 9
// speedup vs baseline: 1.3338x; 1.0229x over previous
#include <cuda_runtime.h>
#include <cuda_fp16.h>
#include <cuda_bf16.h>
#include <cstdint>

// Problem constants (fixed shapes)
#define B 8
#define N 2048
#define F 128            // F_IN == F_OUT == 128
#define MAXN 192         // max neighbors per row (mean ~42)
#define ALPHA 0.2f

// Scratch (no cudaMalloc allowed)
__device__ __align__(16) __half g_hh[B * N * F];   // 4 MB, fp16 copy of h
__device__ float g_esrc[B * N];
__device__ float g_edst[B * N];
__device__ int   g_nbr[N * MAXN];
__device__ int   g_nnz[N];

// ---------------------------------------------------------------------------
// mma / ldmatrix helpers
// ---------------------------------------------------------------------------
__device__ __forceinline__ void ldsm_x4(uint32_t* r, uint32_t addr) {
    asm volatile("ldmatrix.sync.aligned.m8n8.x4.shared.b16 {%0,%1,%2,%3}, [%4];"
                 : "=r"(r[0]), "=r"(r[1]), "=r"(r[2]), "=r"(r[3]) : "r"(addr));
}
__device__ __forceinline__ void ldsm_x4_t(uint32_t* r, uint32_t addr) {
    asm volatile("ldmatrix.sync.aligned.m8n8.x4.trans.shared.b16 {%0,%1,%2,%3}, [%4];"
                 : "=r"(r[0]), "=r"(r[1]), "=r"(r[2]), "=r"(r[3]) : "r"(addr));
}
__device__ __forceinline__ void mma_bf16(float* c, const uint32_t* a,
                                         uint32_t b0, uint32_t b1) {
    asm volatile(
        "mma.sync.aligned.m16n8k16.row.col.f32.bf16.bf16.f32 "
        "{%0,%1,%2,%3}, {%4,%5,%6,%7}, {%8,%9}, {%0,%1,%2,%3};"
        : "+f"(c[0]), "+f"(c[1]), "+f"(c[2]), "+f"(c[3])
        : "r"(a[0]), "r"(a[1]), "r"(a[2]), "r"(a[3]), "r"(b0), "r"(b1));
}
__device__ __forceinline__ uint32_t pack_bf16(__nv_bfloat16 a, __nv_bfloat16 b) {
    __nv_bfloat162 t;
    t.x = a; t.y = b;
    return *reinterpret_cast<uint32_t*>(&t);
}

// packed f32x2 fma: acc = w2 * v + acc (both halves)
__device__ __forceinline__ void fma_f32x2(unsigned long long& acc,
                                          unsigned long long w2,
                                          unsigned long long v) {
    asm("fma.rn.f32x2 %0, %1, %2, %0;" : "+l"(acc) : "l"(w2), "l"(v));
}
union F2U { float2 f; unsigned long long u; };

// ---------------------------------------------------------------------------
// Fat kernel: blocks [0, 512)   -> bf16-split mma GEMM h = x@W (+edge terms)
//             blocks [512,1536) -> adjacency compaction, 2 rows each
// ---------------------------------------------------------------------------
#define GEMM_BLOCKS 512
#define ADJ_BLOCKS 1024
#define TM 32
#define KCH 32
#define XSTR 40      // bf16 elems per X smem row
#define WSTR 136     // bf16 elems per W smem row

__global__ __launch_bounds__(64) void fused_gemm_adj_kernel(
    const float* __restrict__ x,
    const float* __restrict__ adj,
    const float* __restrict__ W,
    const float* __restrict__ a_src,
    const float* __restrict__ a_dst) {

    if (blockIdx.x >= GEMM_BLOCKS) {
        // ---------------- adjacency compaction path (float4 scans) ----------
        int i = (blockIdx.x - GEMM_BLOCKS) * 2 + (threadIdx.x >> 5);
        int lane = threadIdx.x & 31;
        const float4* row4 = reinterpret_cast<const float4*>(adj + (size_t)i * N);
        int count = 0;
#pragma unroll 4
        for (int c = 0; c < N / 4; c += 32) {       // 16 iterations
            float4 v = row4[c + lane];
            int base = (c + lane) * 4;
            float vv[4] = {v.x, v.y, v.z, v.w};
#pragma unroll
            for (int k = 0; k < 4; k++) {
                int col = base + k;
                bool p = (vv[k] != 0.f) || (col == i);
                unsigned m = __ballot_sync(0xFFFFFFFFu, p);
                if (p) {
                    int pos = count + __popc(m & ((1u << lane) - 1u));
                    if (pos < MAXN) g_nbr[i * MAXN + pos] = col;
                }
                count += __popc(m);
            }
        }
        if (lane == 0) g_nnz[i] = count < MAXN ? count : MAXN;
        return;
    }

    // ---------------- GEMM path ----------------
    __shared__ __align__(16) __nv_bfloat16 Xhi[TM * XSTR];
    __shared__ __align__(16) __nv_bfloat16 Xlo[TM * XSTR];
    __shared__ __align__(16) __nv_bfloat16 Whi[KCH * WSTR];
    __shared__ __align__(16) __nv_bfloat16 Wlo[KCH * WSTR];

    const int tid = threadIdx.x;
    const int w = tid >> 5;
    const int lane = tid & 31;
    const int m0 = blockIdx.x * TM;

    const int lm = lane >> 3;
    const int lr = lane & 7;
    const int arow = w * 16 + ((lm & 1) << 3) + lr;
    const int acol = (lm >> 1) << 3;
    const int bk = ((lm & 1) << 3) + lr;
    const int bn = (lm >> 1) << 3;

    const uint32_t xhi_b = (uint32_t)__cvta_generic_to_shared(Xhi);
    const uint32_t xlo_b = (uint32_t)__cvta_generic_to_shared(Xlo);
    const uint32_t whi_b = (uint32_t)__cvta_generic_to_shared(Whi);
    const uint32_t wlo_b = (uint32_t)__cvta_generic_to_shared(Wlo);

    float c[16][4];
#pragma unroll
    for (int nt = 0; nt < 16; nt++)
#pragma unroll
        for (int q = 0; q < 4; q++) c[nt][q] = 0.f;

#pragma unroll
    for (int k0 = 0; k0 < F; k0 += KCH) {
#pragma unroll
        for (int it = 0; it < 4; it++) {
            int l = tid + it * 64;
            int row = l >> 3;
            int c4 = l & 7;
            float4 v = reinterpret_cast<const float4*>(
                x + (size_t)(m0 + row) * F + k0)[c4];
            float vv[4] = {v.x, v.y, v.z, v.w};
            __nv_bfloat16 hi[4], lo[4];
#pragma unroll
            for (int j = 0; j < 4; j++) {
                hi[j] = __float2bfloat16_rn(vv[j]);
                lo[j] = __float2bfloat16_rn(vv[j] - __bfloat162float(hi[j]));
            }
            int eoff = row * XSTR + c4 * 4;
            uint2 ph = {pack_bf16(hi[0], hi[1]), pack_bf16(hi[2], hi[3])};
            uint2 pl = {pack_bf16(lo[0], lo[1]), pack_bf16(lo[2], lo[3])};
            *reinterpret_cast<uint2*>(Xhi + eoff) = ph;
            *reinterpret_cast<uint2*>(Xlo + eoff) = pl;
        }
#pragma unroll
        for (int it = 0; it < 16; it++) {
            int l = tid + it * 64;
            int kk = l >> 5;
            int c4 = l & 31;
            float4 v = reinterpret_cast<const float4*>(
                W + (size_t)(k0 + kk) * F)[c4];
            float vv[4] = {v.x, v.y, v.z, v.w};
            __nv_bfloat16 hi[4], lo[4];
#pragma unroll
            for (int j = 0; j < 4; j++) {
                hi[j] = __float2bfloat16_rn(vv[j]);
                lo[j] = __float2bfloat16_rn(vv[j] - __bfloat162float(hi[j]));
            }
            int eoff = kk * WSTR + c4 * 4;
            uint2 ph = {pack_bf16(hi[0], hi[1]), pack_bf16(hi[2], hi[3])};
            uint2 pl = {pack_bf16(lo[0], lo[1]), pack_bf16(lo[2], lo[3])};
            *reinterpret_cast<uint2*>(Whi + eoff) = ph;
            *reinterpret_cast<uint2*>(Wlo + eoff) = pl;
        }
        __syncthreads();

#pragma unroll
        for (int ks = 0; ks < KCH; ks += 16) {
            uint32_t ah[4], al[4];
            uint32_t aoff = (uint32_t)((arow * XSTR + ks + acol) * 2);
            ldsm_x4(ah, xhi_b + aoff);
            ldsm_x4(al, xlo_b + aoff);
#pragma unroll
            for (int np = 0; np < 8; np++) {
                uint32_t bh[4], bl[4];
                uint32_t boff = (uint32_t)(((ks + bk) * WSTR + np * 16 + bn) * 2);
                ldsm_x4_t(bh, whi_b + boff);
                ldsm_x4_t(bl, wlo_b + boff);
                mma_bf16(c[2 * np],     ah, bh[0], bh[1]);
                mma_bf16(c[2 * np],     ah, bl[0], bl[1]);
                mma_bf16(c[2 * np],     al, bh[0], bh[1]);
                mma_bf16(c[2 * np + 1], ah, bh[2], bh[3]);
                mma_bf16(c[2 * np + 1], ah, bl[2], bl[3]);
                mma_bf16(c[2 * np + 1], al, bh[2], bh[3]);
            }
        }
        __syncthreads();
    }

    const int gid = lane >> 2;
    const int tig = lane & 3;
    const int r0 = m0 + w * 16 + gid;
    const int r1 = r0 + 8;

    float ss0 = 0.f, sd0 = 0.f, ss1 = 0.f, sd1 = 0.f;
#pragma unroll
    for (int nt = 0; nt < 16; nt++) {
        int col = nt * 8 + tig * 2;
        __half2 p0 = __floats2half2_rn(c[nt][0], c[nt][1]);
        __half2 p1 = __floats2half2_rn(c[nt][2], c[nt][3]);
        *reinterpret_cast<__half2*>(g_hh + (size_t)r0 * F + col) = p0;
        *reinterpret_cast<__half2*>(g_hh + (size_t)r1 * F + col) = p1;
        float as0 = a_src[col], as1 = a_src[col + 1];
        float ad0 = a_dst[col], ad1 = a_dst[col + 1];
        ss0 += c[nt][0] * as0 + c[nt][1] * as1;
        sd0 += c[nt][0] * ad0 + c[nt][1] * ad1;
        ss1 += c[nt][2] * as0 + c[nt][3] * as1;
        sd1 += c[nt][2] * ad0 + c[nt][3] * ad1;
    }
#pragma unroll
    for (int o = 1; o <= 2; o <<= 1) {
        ss0 += __shfl_xor_sync(0xFFFFFFFFu, ss0, o);
        sd0 += __shfl_xor_sync(0xFFFFFFFFu, sd0, o);
        ss1 += __shfl_xor_sync(0xFFFFFFFFu, ss1, o);
        sd1 += __shfl_xor_sync(0xFFFFFFFFu, sd1, o);
    }
    if (tig == 0) {
        g_esrc[r0] = ss0;
        g_edst[r0] = sd0;
        g_esrc[r1] = ss1;
        g_edst[r1] = sd1;
    }
}

// ---------------------------------------------------------------------------
// Kernel 2: HALF-WARP per (b,i): sparse softmax + LDG.128 fp16 gather + ELU.
// 256 threads = 16 half-warps per block; each lane16 owns 8 output columns.
// All sub-warp shuffles/syncs use the half-warp's own mask (the two half-
// warps of a warp diverge on nnz).
// ---------------------------------------------------------------------------
#define ROWS_PER_BLK 16
__global__ __launch_bounds__(256) void agg_kernel(float* __restrict__ out) {
    __shared__ int   s_idx[ROWS_PER_BLK][MAXN];
    __shared__ float s_w[ROWS_PER_BLK][MAXN];

    const int hw = threadIdx.x >> 4;       // half-warp id 0..15
    const int l = threadIdx.x & 15;        // lane within half-warp
    const unsigned hmask = 0xFFFFu << (threadIdx.x & 16);  // this half-warp's lanes
    const int wg = blockIdx.x * ROWS_PER_BLK + hw;  // row id in [0, B*N)
    const int b = wg >> 11;
    const int i = wg & (N - 1);

    const int nnz = g_nnz[i];
    const float ei = g_esrc[wg];
    const float* __restrict__ edst_b = g_edst + b * N;
    const int* __restrict__ nbr = g_nbr + i * MAXN;

    // Pass 1: logits -> shared, max (width-16 reduction, half-warp mask)
    float m = -1e30f;
    for (int j = l; j < nnz; j += 16) {
        int col = nbr[j];
        float v = ei + edst_b[col];
        v = (v >= 0.f) ? v : ALPHA * v;   // LeakyReLU
        s_idx[hw][j] = col;
        s_w[hw][j] = v;
        m = fmaxf(m, v);
    }
#pragma unroll
    for (int o = 8; o; o >>= 1) m = fmaxf(m, __shfl_xor_sync(hmask, m, o, 16));

    __syncwarp(hmask);
    // Pass 2: exp + sum
    float sum = 0.f;
    for (int j = l; j < nnz; j += 16) {
        float e = expf(s_w[hw][j] - m);
        s_w[hw][j] = e;
        sum += e;
    }
#pragma unroll
    for (int o = 8; o; o >>= 1) sum += __shfl_xor_sync(hmask, sum, o, 16);
    const float inv = 1.f / sum;
    __syncwarp(hmask);

    // Pass 3: gather-aggregate. Lane owns cols [l*8, l*8+8): one uint4 per nbr.
    const __half* __restrict__ hb = g_hh + (size_t)b * N * F;
    unsigned long long acc0 = 0ull, acc1 = 0ull, acc2 = 0ull, acc3 = 0ull;
    int j = 0;
    for (; j + 4 <= nnz; j += 4) {
        uint4 r[4];
        unsigned long long wp[4];
#pragma unroll
        for (int q = 0; q < 4; q++) {
            int ij = s_idx[hw][j + q];
            uint32_t wu = __float_as_uint(s_w[hw][j + q]);
            asm("mov.b64 %0, {%1,%1};" : "=l"(wp[q]) : "r"(wu));
            r[q] = reinterpret_cast<const uint4*>(hb + (size_t)ij * F)[l];
        }
#pragma unroll
        for (int q = 0; q < 4; q++) {
            const __half2* h2 = reinterpret_cast<const __half2*>(&r[q]);
            F2U v0, v1, v2, v3;
            v0.f = __half22float2(h2[0]);
            v1.f = __half22float2(h2[1]);
            v2.f = __half22float2(h2[2]);
            v3.f = __half22float2(h2[3]);
            fma_f32x2(acc0, wp[q], v0.u);
            fma_f32x2(acc1, wp[q], v1.u);
            fma_f32x2(acc2, wp[q], v2.u);
            fma_f32x2(acc3, wp[q], v3.u);
        }
    }
    for (; j < nnz; j++) {
        int ij = s_idx[hw][j];
        uint32_t wu = __float_as_uint(s_w[hw][j]);
        unsigned long long wp;
        asm("mov.b64 %0, {%1,%1};" : "=l"(wp) : "r"(wu));
        uint4 r = reinterpret_cast<const uint4*>(hb + (size_t)ij * F)[l];
        const __half2* h2 = reinterpret_cast<const __half2*>(&r);
        F2U v0, v1, v2, v3;
        v0.f = __half22float2(h2[0]);
        v1.f = __half22float2(h2[1]);
        v2.f = __half22float2(h2[2]);
        v3.f = __half22float2(h2[3]);
        fma_f32x2(acc0, wp, v0.u);
        fma_f32x2(acc1, wp, v1.u);
        fma_f32x2(acc2, wp, v2.u);
        fma_f32x2(acc3, wp, v3.u);
    }

    // Normalize + ELU + store 8 floats (explicit float4s, no aliasing)
    F2U a0, a1, a2, a3;
    a0.u = acc0; a1.u = acc1; a2.u = acc2; a3.u = acc3;
#define ELU1(t) ((t) > 0.f ? (t) : expm1f(t))
    float4 o0 = make_float4(ELU1(a0.f.x * inv), ELU1(a0.f.y * inv),
                            ELU1(a1.f.x * inv), ELU1(a1.f.y * inv));
    float4 o1 = make_float4(ELU1(a2.f.x * inv), ELU1(a2.f.y * inv),
                            ELU1(a3.f.x * inv), ELU1(a3.f.y * inv));
#undef ELU1
    float* dst = out + (size_t)wg * F + l * 8;
    reinterpret_cast<float4*>(dst)[0] = o0;
    reinterpret_cast<float4*>(dst)[1] = o1;
}

// ---------------------------------------------------------------------------
extern "C" void kernel_launch(void* const* d_in, const int* in_sizes, int n_in,
                              void* d_out, int out_size) {
    const float* x     = (const float*)d_in[0];  // [B, N, F]
    const float* adj   = (const float*)d_in[1];  // [N, N]
    const float* W     = (const float*)d_in[2];  // [F, F]
    const float* a_src = (const float*)d_in[3];  // [F]
    const float* a_dst = (const float*)d_in[4];  // [F]
    float* out = (float*)d_out;                  // [B, N, F]

    (void)in_sizes; (void)n_in; (void)out_size;

    fused_gemm_adj_kernel<<<GEMM_BLOCKS + ADJ_BLOCKS, 64>>>(x, adj, W, a_src, a_dst);
    agg_kernel<<<(B * N) / ROWS_PER_BLK, 256>>>(out);
}

// round 10
// speedup vs baseline: 1.4992x; 1.1240x over previous
#include <cuda_runtime.h>
#include <cuda_fp16.h>
#include <cuda_bf16.h>
#include <cstdint>

// Problem constants (fixed shapes)
#define B 8
#define N 2048
#define F 128            // F_IN == F_OUT == 128
#define MAXN 192         // max neighbors per row (mean ~42)
#define ALPHA 0.2f

// Scratch (no cudaMalloc allowed)
__device__ __align__(16) __half g_hh[B * N * F];   // 4 MB, fp16 copy of h
__device__ float g_esrc[B * N];
__device__ float g_edst[B * N];
__device__ int   g_nbr[N * MAXN];
__device__ int   g_nnz[N];
__device__ __align__(16) __nv_bfloat16 g_Whi[F * F];  // pre-split W
__device__ __align__(16) __nv_bfloat16 g_Wlo[F * F];

// ---------------------------------------------------------------------------
// mma / ldmatrix helpers
// ---------------------------------------------------------------------------
__device__ __forceinline__ void ldsm_x4(uint32_t* r, uint32_t addr) {
    asm volatile("ldmatrix.sync.aligned.m8n8.x4.shared.b16 {%0,%1,%2,%3}, [%4];"
                 : "=r"(r[0]), "=r"(r[1]), "=r"(r[2]), "=r"(r[3]) : "r"(addr));
}
__device__ __forceinline__ void ldsm_x4_t(uint32_t* r, uint32_t addr) {
    asm volatile("ldmatrix.sync.aligned.m8n8.x4.trans.shared.b16 {%0,%1,%2,%3}, [%4];"
                 : "=r"(r[0]), "=r"(r[1]), "=r"(r[2]), "=r"(r[3]) : "r"(addr));
}
__device__ __forceinline__ void mma_bf16(float* c, const uint32_t* a,
                                         uint32_t b0, uint32_t b1) {
    asm volatile(
        "mma.sync.aligned.m16n8k16.row.col.f32.bf16.bf16.f32 "
        "{%0,%1,%2,%3}, {%4,%5,%6,%7}, {%8,%9}, {%0,%1,%2,%3};"
        : "+f"(c[0]), "+f"(c[1]), "+f"(c[2]), "+f"(c[3])
        : "r"(a[0]), "r"(a[1]), "r"(a[2]), "r"(a[3]), "r"(b0), "r"(b1));
}
__device__ __forceinline__ uint32_t pack_bf16(__nv_bfloat16 a, __nv_bfloat16 b) {
    __nv_bfloat162 t;
    t.x = a; t.y = b;
    return *reinterpret_cast<uint32_t*>(&t);
}
__device__ __forceinline__ void fma_f32x2(unsigned long long& acc,
                                          unsigned long long w2,
                                          unsigned long long v) {
    asm("fma.rn.f32x2 %0, %1, %2, %0;" : "+l"(acc) : "l"(w2), "l"(v));
}
union F2U { float2 f; unsigned long long u; };

// ---------------------------------------------------------------------------
// Kernel 0 (prep): split W into bf16 hi/lo once. 32 blocks x 128 thr x 4 elems.
// ---------------------------------------------------------------------------
__global__ __launch_bounds__(128) void wsplit_kernel(const float* __restrict__ W) {
    int idx = (blockIdx.x * 128 + threadIdx.x) * 4;
    float4 v = *reinterpret_cast<const float4*>(W + idx);
    float vv[4] = {v.x, v.y, v.z, v.w};
    __nv_bfloat16 hi[4], lo[4];
#pragma unroll
    for (int j = 0; j < 4; j++) {
        hi[j] = __float2bfloat16_rn(vv[j]);
        lo[j] = __float2bfloat16_rn(vv[j] - __bfloat162float(hi[j]));
    }
    uint2 ph = {pack_bf16(hi[0], hi[1]), pack_bf16(hi[2], hi[3])};
    uint2 pl = {pack_bf16(lo[0], lo[1]), pack_bf16(lo[2], lo[3])};
    *reinterpret_cast<uint2*>(g_Whi + idx) = ph;
    *reinterpret_cast<uint2*>(g_Wlo + idx) = pl;
}

// ---------------------------------------------------------------------------
// Fat kernel (128 thr): blocks [0,256)    -> bf16-split mma GEMM, 64 rows each
//                       blocks [256,768)  -> adj compaction, 4 rows each (1/warp)
// ---------------------------------------------------------------------------
#define GEMM_BLOCKS 256
#define ADJ_BLOCKS 512
#define TM 64
#define KCH 32
#define XSTR 40      // bf16 elems per X smem row
#define WSTR 136     // bf16 elems per W smem row

__global__ __launch_bounds__(128) void fused_gemm_adj_kernel(
    const float* __restrict__ x,
    const float* __restrict__ adj,
    const float* __restrict__ a_src,
    const float* __restrict__ a_dst) {

    if (blockIdx.x >= GEMM_BLOCKS) {
        // ------- adjacency: single-pass bitmask compaction, warp per row -----
        int i = (blockIdx.x - GEMM_BLOCKS) * 4 + (threadIdx.x >> 5);
        int lane = threadIdx.x & 31;
        const float4* row4 = reinterpret_cast<const float4*>(adj + (size_t)i * N);
        // lane owns cols [lane*64, lane*64+64): 16 float4 loads, full MLP
        unsigned msk0 = 0u, msk1 = 0u;
        int cnt = 0;
#pragma unroll
        for (int q = 0; q < 16; q++) {
            float4 v = row4[lane * 16 + q];
            int base = q * 4;
            float vv[4] = {v.x, v.y, v.z, v.w};
#pragma unroll
            for (int k = 0; k < 4; k++) {
                int bit = base + k;
                bool p = (vv[k] != 0.f) || (lane * 64 + bit == i);
                if (p) {
                    if (bit < 32) msk0 |= (1u << bit);
                    else          msk1 |= (1u << (bit - 32));
                    cnt++;
                }
            }
        }
        // exclusive scan of cnt across lanes
        int off = cnt;
#pragma unroll
        for (int d = 1; d < 32; d <<= 1) {
            int t = __shfl_up_sync(0xFFFFFFFFu, off, d);
            if (lane >= d) off += t;
        }
        int total = __shfl_sync(0xFFFFFFFFu, off, 31);
        off -= cnt;
        // emit indices (ascending column order)
        int pos = off;
        unsigned mm = msk0;
        while (mm) {
            int bit = __ffs(mm) - 1;
            mm &= mm - 1;
            if (pos < MAXN) g_nbr[i * MAXN + pos] = lane * 64 + bit;
            pos++;
        }
        mm = msk1;
        while (mm) {
            int bit = __ffs(mm) - 1;
            mm &= mm - 1;
            if (pos < MAXN) g_nbr[i * MAXN + pos] = lane * 64 + 32 + bit;
            pos++;
        }
        if (lane == 31) g_nnz[i] = total < MAXN ? total : MAXN;
        return;
    }

    // ---------------- GEMM path: 4 warps, 16 rows each ----------------
    __shared__ __align__(16) __nv_bfloat16 Xhi[TM * XSTR];
    __shared__ __align__(16) __nv_bfloat16 Xlo[TM * XSTR];
    __shared__ __align__(16) __nv_bfloat16 Whi[KCH * WSTR];
    __shared__ __align__(16) __nv_bfloat16 Wlo[KCH * WSTR];

    const int tid = threadIdx.x;
    const int w = tid >> 5;
    const int lane = tid & 31;
    const int m0 = blockIdx.x * TM;

    const int lm = lane >> 3;
    const int lr = lane & 7;
    const int arow = w * 16 + ((lm & 1) << 3) + lr;
    const int acol = (lm >> 1) << 3;
    const int bk = ((lm & 1) << 3) + lr;
    const int bn = (lm >> 1) << 3;

    const uint32_t xhi_b = (uint32_t)__cvta_generic_to_shared(Xhi);
    const uint32_t xlo_b = (uint32_t)__cvta_generic_to_shared(Xlo);
    const uint32_t whi_b = (uint32_t)__cvta_generic_to_shared(Whi);
    const uint32_t wlo_b = (uint32_t)__cvta_generic_to_shared(Wlo);

    float c[16][4];
#pragma unroll
    for (int nt = 0; nt < 16; nt++)
#pragma unroll
        for (int q = 0; q < 4; q++) c[nt][q] = 0.f;

#pragma unroll
    for (int k0 = 0; k0 < F; k0 += KCH) {
        // ---- X chunk [64 rows x 32 k]: load fp32, split inline ----
#pragma unroll
        for (int it = 0; it < 4; it++) {
            int l = tid + it * 128;
            int row = l >> 3;
            int c4 = l & 7;
            float4 v = reinterpret_cast<const float4*>(
                x + (size_t)(m0 + row) * F + k0)[c4];
            float vv[4] = {v.x, v.y, v.z, v.w};
            __nv_bfloat16 hi[4], lo[4];
#pragma unroll
            for (int j = 0; j < 4; j++) {
                hi[j] = __float2bfloat16_rn(vv[j]);
                lo[j] = __float2bfloat16_rn(vv[j] - __bfloat162float(hi[j]));
            }
            int eoff = row * XSTR + c4 * 4;
            uint2 ph = {pack_bf16(hi[0], hi[1]), pack_bf16(hi[2], hi[3])};
            uint2 pl = {pack_bf16(lo[0], lo[1]), pack_bf16(lo[2], lo[3])};
            *reinterpret_cast<uint2*>(Xhi + eoff) = ph;
            *reinterpret_cast<uint2*>(Xlo + eoff) = pl;
        }
        // ---- W chunk [32 k x 128 n]: pre-split bf16, straight copy ----
#pragma unroll
        for (int it = 0; it < 4; it++) {
            int l = tid + it * 128;       // 0..511
            int kk = l >> 4;              // 0..31
            int c8 = l & 15;              // uint4 = 8 bf16
            reinterpret_cast<uint4*>(Whi + kk * WSTR + c8 * 8)[0] =
                reinterpret_cast<const uint4*>(g_Whi + (size_t)(k0 + kk) * F + c8 * 8)[0];
            reinterpret_cast<uint4*>(Wlo + kk * WSTR + c8 * 8)[0] =
                reinterpret_cast<const uint4*>(g_Wlo + (size_t)(k0 + kk) * F + c8 * 8)[0];
        }
        __syncthreads();

#pragma unroll
        for (int ks = 0; ks < KCH; ks += 16) {
            uint32_t ah[4], al[4];
            uint32_t aoff = (uint32_t)((arow * XSTR + ks + acol) * 2);
            ldsm_x4(ah, xhi_b + aoff);
            ldsm_x4(al, xlo_b + aoff);
#pragma unroll
            for (int np = 0; np < 8; np++) {
                uint32_t bh[4], bl[4];
                uint32_t boff = (uint32_t)(((ks + bk) * WSTR + np * 16 + bn) * 2);
                ldsm_x4_t(bh, whi_b + boff);
                ldsm_x4_t(bl, wlo_b + boff);
                mma_bf16(c[2 * np],     ah, bh[0], bh[1]);
                mma_bf16(c[2 * np],     ah, bl[0], bl[1]);
                mma_bf16(c[2 * np],     al, bh[0], bh[1]);
                mma_bf16(c[2 * np + 1], ah, bh[2], bh[3]);
                mma_bf16(c[2 * np + 1], ah, bl[2], bl[3]);
                mma_bf16(c[2 * np + 1], al, bh[2], bh[3]);
            }
        }
        __syncthreads();
    }

    // ---- epilogue: h (fp16) store + fused edge terms ----
    const int gid = lane >> 2;
    const int tig = lane & 3;
    const int r0 = m0 + w * 16 + gid;
    const int r1 = r0 + 8;

    float ss0 = 0.f, sd0 = 0.f, ss1 = 0.f, sd1 = 0.f;
#pragma unroll
    for (int nt = 0; nt < 16; nt++) {
        int col = nt * 8 + tig * 2;
        __half2 p0 = __floats2half2_rn(c[nt][0], c[nt][1]);
        __half2 p1 = __floats2half2_rn(c[nt][2], c[nt][3]);
        *reinterpret_cast<__half2*>(g_hh + (size_t)r0 * F + col) = p0;
        *reinterpret_cast<__half2*>(g_hh + (size_t)r1 * F + col) = p1;
        float as0 = a_src[col], as1 = a_src[col + 1];
        float ad0 = a_dst[col], ad1 = a_dst[col + 1];
        ss0 += c[nt][0] * as0 + c[nt][1] * as1;
        sd0 += c[nt][0] * ad0 + c[nt][1] * ad1;
        ss1 += c[nt][2] * as0 + c[nt][3] * as1;
        sd1 += c[nt][2] * ad0 + c[nt][3] * ad1;
    }
#pragma unroll
    for (int o = 1; o <= 2; o <<= 1) {
        ss0 += __shfl_xor_sync(0xFFFFFFFFu, ss0, o);
        sd0 += __shfl_xor_sync(0xFFFFFFFFu, sd0, o);
        ss1 += __shfl_xor_sync(0xFFFFFFFFu, ss1, o);
        sd1 += __shfl_xor_sync(0xFFFFFFFFu, sd1, o);
    }
    if (tig == 0) {
        g_esrc[r0] = ss0;
        g_edst[r0] = sd0;
        g_esrc[r1] = ss1;
        g_edst[r1] = sd1;
    }
}

// ---------------------------------------------------------------------------
// Kernel 2: HALF-WARP per (b,i). 128 thr = 8 half-warps; grid 2048.
// Lane16 owns 8 output columns; LDG.128 gathers; fp32x2 packed FMA.
// ---------------------------------------------------------------------------
#define ROWS_PER_BLK 8
__global__ __launch_bounds__(128) void agg_kernel(float* __restrict__ out) {
    __shared__ int   s_idx[ROWS_PER_BLK][MAXN];
    __shared__ float s_w[ROWS_PER_BLK][MAXN];

    const int hw = threadIdx.x >> 4;
    const int l = threadIdx.x & 15;
    const unsigned hmask = 0xFFFFu << (threadIdx.x & 16);
    const int wg = blockIdx.x * ROWS_PER_BLK + hw;
    const int b = wg >> 11;
    const int i = wg & (N - 1);

    const int nnz = g_nnz[i];
    const float ei = g_esrc[wg];
    const float* __restrict__ edst_b = g_edst + b * N;
    const int* __restrict__ nbr = g_nbr + i * MAXN;

    // Pass 1: logits -> shared, max
    float m = -1e30f;
    for (int j = l; j < nnz; j += 16) {
        int col = nbr[j];
        float v = ei + edst_b[col];
        v = (v >= 0.f) ? v : ALPHA * v;   // LeakyReLU
        s_idx[hw][j] = col;
        s_w[hw][j] = v;
        m = fmaxf(m, v);
    }
#pragma unroll
    for (int o = 8; o; o >>= 1) m = fmaxf(m, __shfl_xor_sync(hmask, m, o, 16));

    __syncwarp(hmask);
    // Pass 2: exp + sum
    float sum = 0.f;
    for (int j = l; j < nnz; j += 16) {
        float e = expf(s_w[hw][j] - m);
        s_w[hw][j] = e;
        sum += e;
    }
#pragma unroll
    for (int o = 8; o; o >>= 1) sum += __shfl_xor_sync(hmask, sum, o, 16);
    const float inv = 1.f / sum;
    __syncwarp(hmask);

    // Pass 3: gather-aggregate, unroll 8 (deep L1tex queue)
    const __half* __restrict__ hb = g_hh + (size_t)b * N * F;
    unsigned long long acc0 = 0ull, acc1 = 0ull, acc2 = 0ull, acc3 = 0ull;
    int j = 0;
    for (; j + 8 <= nnz; j += 8) {
        uint4 r[8];
        unsigned long long wp[8];
#pragma unroll
        for (int q = 0; q < 8; q++) {
            int ij = s_idx[hw][j + q];
            uint32_t wu = __float_as_uint(s_w[hw][j + q]);
            asm("mov.b64 %0, {%1,%1};" : "=l"(wp[q]) : "r"(wu));
            r[q] = reinterpret_cast<const uint4*>(hb + (size_t)ij * F)[l];
        }
#pragma unroll
        for (int q = 0; q < 8; q++) {
            const __half2* h2 = reinterpret_cast<const __half2*>(&r[q]);
            F2U v0, v1, v2, v3;
            v0.f = __half22float2(h2[0]);
            v1.f = __half22float2(h2[1]);
            v2.f = __half22float2(h2[2]);
            v3.f = __half22float2(h2[3]);
            fma_f32x2(acc0, wp[q], v0.u);
            fma_f32x2(acc1, wp[q], v1.u);
            fma_f32x2(acc2, wp[q], v2.u);
            fma_f32x2(acc3, wp[q], v3.u);
        }
    }
    for (; j < nnz; j++) {
        int ij = s_idx[hw][j];
        uint32_t wu = __float_as_uint(s_w[hw][j]);
        unsigned long long wp;
        asm("mov.b64 %0, {%1,%1};" : "=l"(wp) : "r"(wu));
        uint4 r = reinterpret_cast<const uint4*>(hb + (size_t)ij * F)[l];
        const __half2* h2 = reinterpret_cast<const __half2*>(&r);
        F2U v0, v1, v2, v3;
        v0.f = __half22float2(h2[0]);
        v1.f = __half22float2(h2[1]);
        v2.f = __half22float2(h2[2]);
        v3.f = __half22float2(h2[3]);
        fma_f32x2(acc0, wp, v0.u);
        fma_f32x2(acc1, wp, v1.u);
        fma_f32x2(acc2, wp, v2.u);
        fma_f32x2(acc3, wp, v3.u);
    }

    F2U a0, a1, a2, a3;
    a0.u = acc0; a1.u = acc1; a2.u = acc2; a3.u = acc3;
#define ELU1(t) ((t) > 0.f ? (t) : expm1f(t))
    float4 o0 = make_float4(ELU1(a0.f.x * inv), ELU1(a0.f.y * inv),
                            ELU1(a1.f.x * inv), ELU1(a1.f.y * inv));
    float4 o1 = make_float4(ELU1(a2.f.x * inv), ELU1(a2.f.y * inv),
                            ELU1(a3.f.x * inv), ELU1(a3.f.y * inv));
#undef ELU1
    float* dst = out + (size_t)wg * F + l * 8;
    reinterpret_cast<float4*>(dst)[0] = o0;
    reinterpret_cast<float4*>(dst)[1] = o1;
}

// ---------------------------------------------------------------------------
extern "C" void kernel_launch(void* const* d_in, const int* in_sizes, int n_in,
                              void* d_out, int out_size) {
    const float* x     = (const float*)d_in[0];  // [B, N, F]
    const float* adj   = (const float*)d_in[1];  // [N, N]
    const float* W     = (const float*)d_in[2];  // [F, F]
    const float* a_src = (const float*)d_in[3];  // [F]
    const float* a_dst = (const float*)d_in[4];  // [F]
    float* out = (float*)d_out;                  // [B, N, F]

    (void)in_sizes; (void)n_in; (void)out_size;

    wsplit_kernel<<<32, 128>>>(W);
    fused_gemm_adj_kernel<<<GEMM_BLOCKS + ADJ_BLOCKS, 128>>>(x, adj, a_src, a_dst);
    agg_kernel<<<(B * N) / ROWS_PER_BLK, 128>>>(out);
}